// round 9
// baseline (speedup 1.0000x reference)
#include <cuda_runtime.h>
#include <cuda_bf16.h>
#include <cstdint>

// Only Z0[:,:,-1] = conv(X0, t=10) is nonzero.  Softmax degree-norm is a no-op.
// Single persistent kernel, 32 warps/SM, exact-division tiling (all SMs busy
// in every phase), replay-safe grid barriers.

#define NBLK 148
#define NTHR 1024
#define NT (NBLK * NTHR)

// ---------------- device scratch ----------------
__device__ float g_obs2[2 * 8192];     // MLP input rows t=9,10
__device__ float g_s1[2 * 2048];       // accum (no bias), zeroed in P5
__device__ float g_s2[2 * 2048];       // accum, zeroed in P5
__device__ float g_s3[2 * 12288];      // accum; row0=X9, row1=X10 (pre-bias/relu)
__device__ float g_sph[12 * 256];      // accum (no bias), zeroed in P5
__device__ float g_tph[256];           // plain store (pre-bias)
__device__ float g_U[3 * 1024 * 12];   // [c][n][tau], c = feat-9
__device__ float g_Y[1024 * 12];
__device__ float g_G[3 * 1024 * 12];   // normalized (A@X) rows

// ---------------- grid barrier (sense-reversing, replay-safe) --------------
__device__ unsigned g_bar_cnt[8];
__device__ unsigned g_bar_flag[8];

__device__ __forceinline__ void grid_barrier(int i) {
    __syncthreads();
    if (threadIdx.x == 0) {
        volatile unsigned* fl = &g_bar_flag[i];
        unsigned sense = *fl;
        __threadfence();
        unsigned old = atomicAdd(&g_bar_cnt[i], 1);
        if (old == NBLK - 1) {
            g_bar_cnt[i] = 0;
            __threadfence();
            *fl = sense ^ 1u;
        } else {
            while (*fl == sense) { }
        }
        __threadfence();
    }
    __syncthreads();
}

// ---------------- gemv tile: M=2 rows, 4 cols, [k0,k1) chunk ---------------
template<int K, int N, bool RELU>
__device__ __forceinline__ void gemv_tile(const float* __restrict__ A,
                                          const float* __restrict__ bias,
                                          const float* __restrict__ W,
                                          float* __restrict__ S,
                                          int col, int k0, int k1) {
    float a00 = 0, a01 = 0, a02 = 0, a03 = 0;
    float a10 = 0, a11 = 0, a12 = 0, a13 = 0;
#pragma unroll 4
    for (int k = k0; k < k1; ++k) {
        const float4 w = *reinterpret_cast<const float4*>(W + (size_t)k * N + col);
        float x0 = A[k], x1 = A[K + k];
        if (RELU) {
            float bb = bias[k];
            x0 = fmaxf(x0 + bb, 0.0f); x1 = fmaxf(x1 + bb, 0.0f);
        }
        a00 += x0 * w.x; a01 += x0 * w.y; a02 += x0 * w.z; a03 += x0 * w.w;
        a10 += x1 * w.x; a11 += x1 * w.y; a12 += x1 * w.z; a13 += x1 * w.w;
    }
    atomicAdd(S + col + 0, a00); atomicAdd(S + col + 1, a01);
    atomicAdd(S + col + 2, a02); atomicAdd(S + col + 3, a03);
    atomicAdd(S + N + col + 0, a10); atomicAdd(S + N + col + 1, a11);
    atomicAdd(S + N + col + 2, a12); atomicAdd(S + N + col + 3, a13);
}

#define SMEM_FLOATS (3 * 12288)

__device__ __forceinline__ float4 relu4b(float4 v, float4 b) {
    v.x = fmaxf(v.x + b.x, 0.0f); v.y = fmaxf(v.y + b.y, 0.0f);
    v.z = fmaxf(v.z + b.z, 0.0f); v.w = fmaxf(v.w + b.w, 0.0f);
    return v;
}

// ---------------- the single mega kernel ----------------
__global__ void __launch_bounds__(NTHR, 1)
mega5_kernel(const float* __restrict__ obs,
             const float* __restrict__ tf,
             const float* __restrict__ fc_w1, const float* __restrict__ b1,
             const float* __restrict__ fc_w2, const float* __restrict__ b2,
             const float* __restrict__ fc_w3, const float* __restrict__ b3,
             const float* __restrict__ Wf, const float* __restrict__ Wb,
             const float* __restrict__ bvec,
             const float* __restrict__ li,
             const float* __restrict__ gs_w1, const float* __restrict__ gs_b1,
             const float* __restrict__ gs_w2, const float* __restrict__ gs_b2,
             const float* __restrict__ gt_w1, const float* __restrict__ gt_b1,
             const float* __restrict__ gt_w2, const float* __restrict__ gt_b2,
             const float* __restrict__ Bm,
             float* __restrict__ out) {
    extern __shared__ float sm[];
    float* sY   = sm;
    float* sX10 = sm + 12288;
    float* sX9  = sm + 24576;

    const int tid = threadIdx.x, bid = blockIdx.x;
    const int gt = bid * NTHR + tid;
    const int lane = tid & 31;

    // ======== P0: obs gather, out-tail zero, sph split-K (coalesced), tph ==
    if (gt < 16384 + 36864) {
        int i = gt;
        if (i < 16384) {
            int m = i >> 13, k = i & 8191;
            int n = k >> 3, d = k & 7;
            g_obs2[i] = obs[n * 96 + d * 12 + 9 + m];
        } else {
            out[12288 + (i - 16384)] = 0.0f;
        }
    }
    {
        int j = gt - 53248;
        if (j >= 0 && j < 24576) {          // sph: 12 tau x 8 kc x 256 t
            int t = j & 255;
            int rr = j >> 8;                // 0..95
            int tau = rr / 8, kc = rr & 7;
            const float* lr = li + tau * 1024 + kc * 128;
            const float* w  = gs_w1 + (size_t)(kc * 128) * 256 + t;
            float acc = 0.0f;
#pragma unroll 16
            for (int k = 0; k < 128; ++k) acc += lr[k] * w[(size_t)k * 256];
            atomicAdd(&g_sph[tau * 256 + t], acc);
        } else if (j >= 24576 && j < 24832) {   // tph
            int t = j - 24576;
            float acc = 0.0f;
#pragma unroll
            for (int k = 0; k < 36; ++k) acc += tf[k] * gt_w1[k * 256 + t];
            g_tph[t] = acc;                 // bias at read
        }
    }
    grid_barrier(0);

    // ======== P1: gemv1, ALL blocks, 512 col4 x 296 chunks == NT exactly ===
    {
        int col4 = gt & 511;
        int c    = gt >> 9;                 // 0..295
        int k0 = (c * 8192) / 296;
        int k1 = ((c + 1) * 8192) / 296;
        gemv_tile<8192, 2048, false>(g_obs2, b1, fc_w1, g_s1, col4 * 4, k0, k1);
    }
    grid_barrier(1);

    // ======== P2: gemv2 (blocks 0..63, exact)  ||  u-phase (64..147) =======
    if (bid < 64) {
        int lt = bid * NTHR + tid;          // 0..65535 == 512 x 128
        int col4 = lt & 511;
        int kc   = lt >> 9;                 // 0..127, LEN=16
        gemv_tile<2048, 2048, true>(g_s1, b1, fc_w2, g_s2,
                                    col4 * 4, kc * 16, kc * 16 + 16);
    } else {
        int lw = (bid - 64) * 32 + (tid >> 5);   // 0..2687
        for (int task = lw; task < 3072; task += 2688) {
            int n = task / 3, c = task - n * 3;
            int j = n * 12 + 9 + c;
            float wg[8], wt[8], bg[8];
#pragma unroll
            for (int i = 0; i < 8; ++i) {
                int k = lane + 32 * i;
                wg[i] = gs_w2[(size_t)k * 12288 + j];
                wt[i] = gt_w2[(size_t)k * 12288 + j];
                bg[i] = gs_b1[k];
            }
            float tp = 0.0f;
#pragma unroll
            for (int i = 0; i < 8; ++i) {
                int k = lane + 32 * i;
                tp += fmaxf(g_tph[k] + gt_b1[k], 0.0f) * wt[i];
            }
#pragma unroll
            for (int o = 16; o; o >>= 1) tp += __shfl_xor_sync(0xffffffffu, tp, o);
            float tpv = fmaxf(tp + gt_b2[j], 0.0f);
            float bsp = gs_b2[j];
#pragma unroll
            for (int tau = 0; tau < 12; ++tau) {
                float sp = 0.0f;
#pragma unroll
                for (int i = 0; i < 8; ++i)
                    sp += fmaxf(g_sph[tau * 256 + lane + 32 * i] + bg[i], 0.0f) * wg[i];
#pragma unroll
                for (int o = 16; o; o >>= 1) sp += __shfl_xor_sync(0xffffffffu, sp, o);
                if (lane == tau)
                    g_U[c * 12288 + n * 12 + tau] = fmaxf(sp + bsp, 0.0f) + tpv;
            }
        }
    }
    grid_barrier(2);

    // ======== P3: gemv3 (150528 tiles)  +  Y (last 1024 threads) ===========
    if (gt < 150528) {
        int col4 = gt % 3072;
        int c    = gt / 3072;               // 0..48
        int k0 = (c * 2048) / 49;
        int k1 = ((c + 1) * 2048) / 49;
        gemv_tile<2048, 12288, true>(g_s2, b2, fc_w3, g_s3, col4 * 4, k0, k1);
    } else {
        int n = gt - 150528;                // 0..1023
        float u[12];
#pragma unroll
        for (int q = 0; q < 12; ++q) u[q] = g_U[12288 + n * 12 + q];
#pragma unroll
        for (int p = 0; p < 12; ++p) {
            float acc = 0.0f;
#pragma unroll
            for (int q = 0; q < 12; ++q) acc += Bm[p * 12 + q] * u[q];
            g_Y[n * 12 + p] = acc;
        }
    }
    grid_barrier(3);

    // ======== P4: stage Y/X in smem, fused exp-adjacency + SpMM ============
    for (int i = tid; i < 12288 / 4; i += NTHR) {
        ((float4*)sY)[i] = ((const float4*)g_Y)[i];
        float4 bb = ((const float4*)b3)[i % 3072];
        ((float4*)sX10)[i] = relu4b(((const float4*)(g_s3 + 12288))[i], bb);
        ((float4*)sX9)[i]  = relu4b(((const float4*)g_s3)[i], bb);
    }
    __syncthreads();
    {
        int task = gt >> 5;                 // one row per warp; 3072 < 4736
        if (task < 3072) {
            int ap = task >> 10;            // 0..2
            int i = task & 1023;
            int cidx = (ap == 0) ? 1 : (ap == 1 ? 0 : 2);   // a = 10,9,11
            const float* sX = (ap == 0) ? sX10 : sX9;
            float u[12];
#pragma unroll
            for (int q = 0; q < 12; ++q) u[q] = g_U[cidx * 12288 + i * 12 + q];
            float g[12];
#pragma unroll
            for (int q = 0; q < 12; ++q) g[q] = 0.0f;
            float rs = 0.0f;
            for (int j = lane; j < 1024; j += 32) {
                const float4* yr = (const float4*)(sY + j * 12);
                float4 ya = yr[0], yb = yr[1], yc = yr[2];
                float s = u[0]*ya.x + u[1]*ya.y + u[2] *ya.z + u[3] *ya.w
                        + u[4]*yb.x + u[5]*yb.y + u[6] *yb.z + u[7] *yb.w
                        + u[8]*yc.x + u[9]*yc.y + u[10]*yc.z + u[11]*yc.w;
                s = (s >= 0.05f) ? s : 0.0f;
                float e = __expf(s);
                rs += e;
                const float4* xr = (const float4*)(sX + j * 12);
                float4 xa = xr[0], xb = xr[1], xc = xr[2];
                g[0] += e*xa.x; g[1] += e*xa.y; g[2] += e*xa.z; g[3] += e*xa.w;
                g[4] += e*xb.x; g[5] += e*xb.y; g[6] += e*xb.z; g[7] += e*xb.w;
                g[8] += e*xc.x; g[9] += e*xc.y; g[10]+= e*xc.z; g[11]+= e*xc.w;
            }
#pragma unroll
            for (int o = 16; o; o >>= 1) {
                rs += __shfl_xor_sync(0xffffffffu, rs, o);
#pragma unroll
                for (int q = 0; q < 12; ++q)
                    g[q] += __shfl_xor_sync(0xffffffffu, g[q], o);
            }
            if (lane == 0) {
                float inv = 1.0f / rs;
                float* G = g_G + task * 12;
#pragma unroll
                for (int q = 0; q < 12; ++q) G[q] = g[q] * inv;
            }
        }
    }
    grid_barrier(4);

    // ======== P5: combine + zero accumulators ==============================
    if (gt < 12288 + 35840) {
        int idx = gt;
        if (idx < 12288) {
            int n = idx / 12, f = idx % 12;
            float acc1 = bvec[f], acc2 = bvec[f];
#pragma unroll
            for (int q = 0; q < 12; ++q) {
                acc1 += g_G[n * 12 + q] * (Wf[q * 12 + f] + Wb[q * 12 + f]);
                acc2 += g_G[(1024 + n) * 12 + q] * Wf[144 + q * 12 + f]
                      + g_G[(2048 + n) * 12 + q] * Wb[144 + q * 12 + f];
            }
            out[idx] = fmaxf(acc1, 0.0f) + fmaxf(acc2, 0.0f);
        } else {
            int i = idx - 12288;
            if (i < 4096)        g_s1[i] = 0.0f;
            else if (i < 8192)   g_s2[i - 4096] = 0.0f;
            else if (i < 32768)  g_s3[i - 8192] = 0.0f;
            else                 g_sph[i - 32768] = 0.0f;
        }
    }
}

// ---------------- launch ----------------
extern "C" void kernel_launch(void* const* d_in, const int* in_sizes, int n_in,
                              void* d_out, int out_size) {
    const float* obs    = (const float*)d_in[0];
    const float* tf     = (const float*)d_in[1];
    const float* fc_w1  = (const float*)d_in[2];
    const float* fc_b1  = (const float*)d_in[3];
    const float* fc_w2  = (const float*)d_in[4];
    const float* fc_b2  = (const float*)d_in[5];
    const float* fc_w3  = (const float*)d_in[6];
    const float* fc_b3  = (const float*)d_in[7];
    const float* Wf     = (const float*)d_in[8];
    const float* Wb     = (const float*)d_in[9];
    const float* bvec   = (const float*)d_in[10];
    const float* li     = (const float*)d_in[11];
    const float* gs_w1  = (const float*)d_in[12];
    const float* gs_b1  = (const float*)d_in[13];
    const float* gs_w2  = (const float*)d_in[14];
    const float* gs_b2  = (const float*)d_in[15];
    const float* gt_w1  = (const float*)d_in[16];
    const float* gt_b1  = (const float*)d_in[17];
    const float* gt_w2  = (const float*)d_in[18];
    const float* gt_b2  = (const float*)d_in[19];
    const float* Bm     = (const float*)d_in[20];
    float* out = (float*)d_out;

    cudaFuncSetAttribute(mega5_kernel,
                         cudaFuncAttributeMaxDynamicSharedMemorySize,
                         SMEM_FLOATS * sizeof(float));

    mega5_kernel<<<NBLK, NTHR, SMEM_FLOATS * sizeof(float)>>>(
        obs, tf, fc_w1, fc_b1, fc_w2, fc_b2, fc_w3, fc_b3,
        Wf, Wb, bvec, li, gs_w1, gs_b1, gs_w2, gs_b2,
        gt_w1, gt_b1, gt_w2, gt_b2, Bm, out);
}

// round 10
// speedup vs baseline: 1.0003x; 1.0003x over previous
#include <cuda_runtime.h>
#include <cuda_bf16.h>
#include <cstdint>

// Only Z0[:,:,-1] = conv(X0, t=10) is nonzero.  Softmax degree-norm is a no-op.
// Single persistent kernel; per-warp gemv tiles with compile-time LEN and
// exact warp-count division; replay-safe grid barriers.

#define NBLK 148
#define NTHR 1024
#define NT (NBLK * NTHR)
#define NWARP (NBLK * 32)      // 4736

// ---------------- device scratch ----------------
__device__ float g_obs2[2 * 8192];     // MLP input rows t=9,10
__device__ float g_s1[2 * 2048];       // accum (no bias), zeroed in P5
__device__ float g_s2[2 * 2048];       // accum, zeroed in P5
__device__ float g_s3[2 * 12288];      // accum; row0=X9, row1=X10 (pre-bias/relu)
__device__ float g_sph[12 * 256];      // accum (no bias), zeroed in P5
__device__ float g_tph[256];           // plain store (pre-bias)
__device__ float g_U[3 * 1024 * 12];   // [c][n][tau], c = feat-9
__device__ float g_Y[1024 * 12];
__device__ float g_G[3 * 1024 * 12];   // normalized (A@X) rows

// ---------------- grid barrier (sense-reversing, replay-safe) --------------
__device__ unsigned g_bar_cnt[8];
__device__ unsigned g_bar_flag[8];

__device__ __forceinline__ void grid_barrier(int i) {
    __syncthreads();
    if (threadIdx.x == 0) {
        volatile unsigned* fl = &g_bar_flag[i];
        unsigned sense = *fl;
        __threadfence();
        unsigned old = atomicAdd(&g_bar_cnt[i], 1);
        if (old == NBLK - 1) {
            g_bar_cnt[i] = 0;
            __threadfence();
            *fl = sense ^ 1u;
        } else {
            while (*fl == sense) { }
        }
        __threadfence();
    }
    __syncthreads();
}

// ------- per-warp gemv tile: lane owns 4 cols, M=2 rows, LEN k's ----------
template<int K, int N, int LEN, bool RELU>
__device__ __forceinline__ void gemv_wtile(const float* __restrict__ A,
                                           const float* __restrict__ bias,
                                           const float* __restrict__ W,
                                           float* __restrict__ S,
                                           int col, int k0) {
    float a00 = 0, a01 = 0, a02 = 0, a03 = 0;
    float a10 = 0, a11 = 0, a12 = 0, a13 = 0;
#pragma unroll
    for (int kk = 0; kk < LEN; ++kk) {
        int k = k0 + kk;
        const float4 w = *reinterpret_cast<const float4*>(W + (size_t)k * N + col);
        float x0 = A[k], x1 = A[K + k];
        if (RELU) {
            float bb = bias[k];
            x0 = fmaxf(x0 + bb, 0.0f); x1 = fmaxf(x1 + bb, 0.0f);
        }
        a00 += x0 * w.x; a01 += x0 * w.y; a02 += x0 * w.z; a03 += x0 * w.w;
        a10 += x1 * w.x; a11 += x1 * w.y; a12 += x1 * w.z; a13 += x1 * w.w;
    }
    atomicAdd(S + col + 0, a00); atomicAdd(S + col + 1, a01);
    atomicAdd(S + col + 2, a02); atomicAdd(S + col + 3, a03);
    atomicAdd(S + N + col + 0, a10); atomicAdd(S + N + col + 1, a11);
    atomicAdd(S + N + col + 2, a12); atomicAdd(S + N + col + 3, a13);
}

#define SMEM_FLOATS (3 * 12288)

__device__ __forceinline__ float4 relu4b(float4 v, float4 b) {
    v.x = fmaxf(v.x + b.x, 0.0f); v.y = fmaxf(v.y + b.y, 0.0f);
    v.z = fmaxf(v.z + b.z, 0.0f); v.w = fmaxf(v.w + b.w, 0.0f);
    return v;
}

// ---------------- the single mega kernel ----------------
__global__ void __launch_bounds__(NTHR, 1)
mega6_kernel(const float* __restrict__ obs,
             const float* __restrict__ tf,
             const float* __restrict__ fc_w1, const float* __restrict__ b1,
             const float* __restrict__ fc_w2, const float* __restrict__ b2,
             const float* __restrict__ fc_w3, const float* __restrict__ b3,
             const float* __restrict__ Wf, const float* __restrict__ Wb,
             const float* __restrict__ bvec,
             const float* __restrict__ li,
             const float* __restrict__ gs_w1, const float* __restrict__ gs_b1,
             const float* __restrict__ gs_w2, const float* __restrict__ gs_b2,
             const float* __restrict__ gt_w1, const float* __restrict__ gt_b1,
             const float* __restrict__ gt_w2, const float* __restrict__ gt_b2,
             const float* __restrict__ Bm,
             float* __restrict__ out) {
    extern __shared__ float sm[];
    float* sY   = sm;
    float* sX10 = sm + 12288;
    float* sX9  = sm + 24576;

    const int tid = threadIdx.x, bid = blockIdx.x;
    const int gt = bid * NTHR + tid;
    const int lane = tid & 31;
    const int gw = gt >> 5;             // global warp 0..4735

    // ======== P0: obs gather, out-tail zero, sph split-K (coalesced), tph ==
    if (gt < 16384 + 36864) {
        int i = gt;
        if (i < 16384) {
            int m = i >> 13, k = i & 8191;
            int n = k >> 3, d = k & 7;
            g_obs2[i] = obs[n * 96 + d * 12 + 9 + m];
        } else {
            out[12288 + (i - 16384)] = 0.0f;
        }
    }
    {
        int j = gt - 53248;
        if (j >= 0 && j < 24576) {          // sph: 12 tau x 8 kc x 256 t
            int t = j & 255;
            int rr = j >> 8;                // 0..95
            int tau = rr / 8, kc = rr & 7;
            const float* lr = li + tau * 1024 + kc * 128;
            const float* w  = gs_w1 + (size_t)(kc * 128) * 256 + t;
            float acc = 0.0f;
#pragma unroll 16
            for (int k = 0; k < 128; ++k) acc += lr[k] * w[(size_t)k * 256];
            atomicAdd(&g_sph[tau * 256 + t], acc);
        } else if (j >= 24576 && j < 24832) {   // tph
            int t = j - 24576;
            float acc = 0.0f;
#pragma unroll
            for (int k = 0; k < 36; ++k) acc += tf[k] * gt_w1[k * 256 + t];
            g_tph[t] = acc;                 // bias at read
        }
    }
    grid_barrier(0);

    // ======== P1: gemv1 — 16 col-blocks x 296 chunks = 4736 warps exactly ==
    {
        int cb = gw & 15;                   // col-block (128 cols)
        int kc = gw >> 4;                   // 0..295
        int col = (cb * 32 + lane) * 4;
        if (kc < 288)
            gemv_wtile<8192, 2048, 28, false>(g_obs2, b1, fc_w1, g_s1,
                                              col, kc * 28);
        else
            gemv_wtile<8192, 2048, 16, false>(g_obs2, b1, fc_w1, g_s1,
                                              col, 8064 + (kc - 288) * 16);
    }
    grid_barrier(1);

    // ======== P2: gemv2 (blocks 0..63: 2048 warps exact) || u (64..147) ====
    if (bid < 64) {
        int w = bid * 32 + (tid >> 5);      // 0..2047
        int cb = w & 15;
        int kc = w >> 4;                    // 0..127
        int col = (cb * 32 + lane) * 4;
        gemv_wtile<2048, 2048, 16, true>(g_s1, b1, fc_w2, g_s2, col, kc * 16);
    } else {
        int lw = (bid - 64) * 32 + (tid >> 5);   // 0..2687
        for (int task = lw; task < 3072; task += 2688) {
            int n = task / 3, c = task - n * 3;
            int j = n * 12 + 9 + c;
            float wg[8], wt[8], bg[8];
#pragma unroll
            for (int i = 0; i < 8; ++i) {
                int k = lane + 32 * i;
                wg[i] = gs_w2[(size_t)k * 12288 + j];
                wt[i] = gt_w2[(size_t)k * 12288 + j];
                bg[i] = gs_b1[k];
            }
            float tp = 0.0f;
#pragma unroll
            for (int i = 0; i < 8; ++i) {
                int k = lane + 32 * i;
                tp += fmaxf(g_tph[k] + gt_b1[k], 0.0f) * wt[i];
            }
#pragma unroll
            for (int o = 16; o; o >>= 1) tp += __shfl_xor_sync(0xffffffffu, tp, o);
            float tpv = fmaxf(tp + gt_b2[j], 0.0f);
            float bsp = gs_b2[j];
#pragma unroll
            for (int tau = 0; tau < 12; ++tau) {
                float sp = 0.0f;
#pragma unroll
                for (int i = 0; i < 8; ++i)
                    sp += fmaxf(g_sph[tau * 256 + lane + 32 * i] + bg[i], 0.0f) * wg[i];
#pragma unroll
                for (int o = 16; o; o >>= 1) sp += __shfl_xor_sync(0xffffffffu, sp, o);
                if (lane == tau)
                    g_U[c * 12288 + n * 12 + tau] = fmaxf(sp + bsp, 0.0f) + tpv;
            }
        }
    }
    grid_barrier(2);

    // ======== P3: gemv3 — 96 cb x 49 chunks = 4704 warps; last 32 do Y =====
    if (gw < 4704) {
        int cb = gw % 96;
        int kc = gw / 96;                   // 0..48
        int col = (cb * 32 + lane) * 4;
        if (kc < 48)
            gemv_wtile<2048, 12288, 42, true>(g_s2, b2, fc_w3, g_s3,
                                              col, kc * 42);
        else
            gemv_wtile<2048, 12288, 32, true>(g_s2, b2, fc_w3, g_s3,
                                              col, 2016);
    } else {
        int n = (gw - 4704) * 32 + lane;    // 0..1023
        float u[12];
#pragma unroll
        for (int q = 0; q < 12; ++q) u[q] = g_U[12288 + n * 12 + q];
#pragma unroll
        for (int p = 0; p < 12; ++p) {
            float acc = 0.0f;
#pragma unroll
            for (int q = 0; q < 12; ++q) acc += Bm[p * 12 + q] * u[q];
            g_Y[n * 12 + p] = acc;
        }
    }
    grid_barrier(3);

    // ======== P4: stage Y/X in smem, fused exp-adjacency + SpMM ============
    for (int i = tid; i < 12288 / 4; i += NTHR) {
        ((float4*)sY)[i] = ((const float4*)g_Y)[i];
        float4 bb = ((const float4*)b3)[i % 3072];
        ((float4*)sX10)[i] = relu4b(((const float4*)(g_s3 + 12288))[i], bb);
        ((float4*)sX9)[i]  = relu4b(((const float4*)g_s3)[i], bb);
    }
    __syncthreads();
    if (gw < 3072) {                        // one adjacency row per warp
        int ap = gw >> 10;                  // 0..2
        int i = gw & 1023;
        int cidx = (ap == 0) ? 1 : (ap == 1 ? 0 : 2);   // a = 10,9,11
        const float* sX = (ap == 0) ? sX10 : sX9;
        float u[12];
#pragma unroll
        for (int q = 0; q < 12; ++q) u[q] = g_U[cidx * 12288 + i * 12 + q];
        float g[12];
#pragma unroll
        for (int q = 0; q < 12; ++q) g[q] = 0.0f;
        float rs = 0.0f;
        for (int j = lane; j < 1024; j += 32) {
            const float4* yr = (const float4*)(sY + j * 12);
            float4 ya = yr[0], yb = yr[1], yc = yr[2];
            float s = u[0]*ya.x + u[1]*ya.y + u[2] *ya.z + u[3] *ya.w
                    + u[4]*yb.x + u[5]*yb.y + u[6] *yb.z + u[7] *yb.w
                    + u[8]*yc.x + u[9]*yc.y + u[10]*yc.z + u[11]*yc.w;
            s = (s >= 0.05f) ? s : 0.0f;
            float e = __expf(s);
            rs += e;
            const float4* xr = (const float4*)(sX + j * 12);
            float4 xa = xr[0], xb = xr[1], xc = xr[2];
            g[0] += e*xa.x; g[1] += e*xa.y; g[2] += e*xa.z; g[3] += e*xa.w;
            g[4] += e*xb.x; g[5] += e*xb.y; g[6] += e*xb.z; g[7] += e*xb.w;
            g[8] += e*xc.x; g[9] += e*xc.y; g[10]+= e*xc.z; g[11]+= e*xc.w;
        }
#pragma unroll
        for (int o = 16; o; o >>= 1) {
            rs += __shfl_xor_sync(0xffffffffu, rs, o);
#pragma unroll
            for (int q = 0; q < 12; ++q)
                g[q] += __shfl_xor_sync(0xffffffffu, g[q], o);
        }
        if (lane == 0) {
            float inv = 1.0f / rs;
            float* G = g_G + gw * 12;
#pragma unroll
            for (int q = 0; q < 12; ++q) G[q] = g[q] * inv;
        }
    }
    grid_barrier(4);

    // ======== P5: combine + zero accumulators ==============================
    if (gt < 12288 + 35840) {
        int idx = gt;
        if (idx < 12288) {
            int n = idx / 12, f = idx % 12;
            float acc1 = bvec[f], acc2 = bvec[f];
#pragma unroll
            for (int q = 0; q < 12; ++q) {
                acc1 += g_G[n * 12 + q] * (Wf[q * 12 + f] + Wb[q * 12 + f]);
                acc2 += g_G[(1024 + n) * 12 + q] * Wf[144 + q * 12 + f]
                      + g_G[(2048 + n) * 12 + q] * Wb[144 + q * 12 + f];
            }
            out[idx] = fmaxf(acc1, 0.0f) + fmaxf(acc2, 0.0f);
        } else {
            int i = idx - 12288;
            if (i < 4096)        g_s1[i] = 0.0f;
            else if (i < 8192)   g_s2[i - 4096] = 0.0f;
            else if (i < 32768)  g_s3[i - 8192] = 0.0f;
            else                 g_sph[i - 32768] = 0.0f;
        }
    }
}

// ---------------- launch ----------------
extern "C" void kernel_launch(void* const* d_in, const int* in_sizes, int n_in,
                              void* d_out, int out_size) {
    const float* obs    = (const float*)d_in[0];
    const float* tf     = (const float*)d_in[1];
    const float* fc_w1  = (const float*)d_in[2];
    const float* fc_b1  = (const float*)d_in[3];
    const float* fc_w2  = (const float*)d_in[4];
    const float* fc_b2  = (const float*)d_in[5];
    const float* fc_w3  = (const float*)d_in[6];
    const float* fc_b3  = (const float*)d_in[7];
    const float* Wf     = (const float*)d_in[8];
    const float* Wb     = (const float*)d_in[9];
    const float* bvec   = (const float*)d_in[10];
    const float* li     = (const float*)d_in[11];
    const float* gs_w1  = (const float*)d_in[12];
    const float* gs_b1  = (const float*)d_in[13];
    const float* gs_w2  = (const float*)d_in[14];
    const float* gs_b2  = (const float*)d_in[15];
    const float* gt_w1  = (const float*)d_in[16];
    const float* gt_b1  = (const float*)d_in[17];
    const float* gt_w2  = (const float*)d_in[18];
    const float* gt_b2  = (const float*)d_in[19];
    const float* Bm     = (const float*)d_in[20];
    float* out = (float*)d_out;

    cudaFuncSetAttribute(mega6_kernel,
                         cudaFuncAttributeMaxDynamicSharedMemorySize,
                         SMEM_FLOATS * sizeof(float));

    mega6_kernel<<<NBLK, NTHR, SMEM_FLOATS * sizeof(float)>>>(
        obs, tf, fc_w1, fc_b1, fc_w2, fc_b2, fc_w3, fc_b3,
        Wf, Wb, bvec, li, gs_w1, gs_b1, gs_w2, gs_b2,
        gt_w1, gt_b1, gt_w2, gt_b2, Bm, out);
}

// round 11
// speedup vs baseline: 1.1356x; 1.1353x over previous
#include <cuda_runtime.h>
#include <cuda_bf16.h>
#include <cstdint>

// Only Z0[:,:,-1] = conv(X0, t=10) is nonzero.  Softmax degree-norm is a no-op.
// Single persistent kernel; 512 thr/block (high per-thread MLP), exact per-warp
// gemv tiling with compile-time LEN; replay-safe grid barriers.

#define NBLK 148
#define NTHR 512
#define NT (NBLK * NTHR)        // 75776
#define NWARP (NBLK * 16)       // 2368

// ---------------- device scratch ----------------
__device__ float g_obs2[2 * 8192];     // MLP input rows t=9,10
__device__ float g_s1[2 * 2048];       // accum (no bias), zeroed in P5
__device__ float g_s2[2 * 2048];       // accum, zeroed in P5
__device__ float g_s3[2 * 12288];      // accum; row0=X9, row1=X10 (pre-bias/relu)
__device__ float g_sph[12 * 256];      // accum (no bias), zeroed in P5
__device__ float g_tph[256];           // plain store (pre-bias)
__device__ float g_U[3 * 1024 * 12];   // [c][n][tau], c = feat-9
__device__ float g_Y[1024 * 12];
__device__ float g_G[3 * 1024 * 12];   // normalized (A@X) rows

// ---------------- grid barrier (sense-reversing, replay-safe) --------------
__device__ unsigned g_bar_cnt[8];
__device__ unsigned g_bar_flag[8];

__device__ __forceinline__ void grid_barrier(int i) {
    __syncthreads();
    if (threadIdx.x == 0) {
        volatile unsigned* fl = &g_bar_flag[i];
        unsigned sense = *fl;
        __threadfence();
        unsigned old = atomicAdd(&g_bar_cnt[i], 1);
        if (old == NBLK - 1) {
            g_bar_cnt[i] = 0;
            __threadfence();
            *fl = sense ^ 1u;
        } else {
            while (*fl == sense) { }
        }
        __threadfence();
    }
    __syncthreads();
}

// ------- per-warp gemv tile: lane owns 4 cols, M=2 rows, LEN k's ----------
template<int K, int N, int LEN, bool RELU>
__device__ __forceinline__ void gemv_wtile(const float* __restrict__ A,
                                           const float* __restrict__ bias,
                                           const float* __restrict__ W,
                                           float* __restrict__ S,
                                           int col, int k0) {
    float a00 = 0, a01 = 0, a02 = 0, a03 = 0;
    float a10 = 0, a11 = 0, a12 = 0, a13 = 0;
#pragma unroll 8
    for (int kk = 0; kk < LEN; ++kk) {
        int k = k0 + kk;
        const float4 w = *reinterpret_cast<const float4*>(W + (size_t)k * N + col);
        float x0 = A[k], x1 = A[K + k];
        if (RELU) {
            float bb = bias[k];
            x0 = fmaxf(x0 + bb, 0.0f); x1 = fmaxf(x1 + bb, 0.0f);
        }
        a00 += x0 * w.x; a01 += x0 * w.y; a02 += x0 * w.z; a03 += x0 * w.w;
        a10 += x1 * w.x; a11 += x1 * w.y; a12 += x1 * w.z; a13 += x1 * w.w;
    }
    atomicAdd(S + col + 0, a00); atomicAdd(S + col + 1, a01);
    atomicAdd(S + col + 2, a02); atomicAdd(S + col + 3, a03);
    atomicAdd(S + N + col + 0, a10); atomicAdd(S + N + col + 1, a11);
    atomicAdd(S + N + col + 2, a12); atomicAdd(S + N + col + 3, a13);
}

#define SMEM_FLOATS (3 * 12288)

__device__ __forceinline__ float4 relu4b(float4 v, float4 b) {
    v.x = fmaxf(v.x + b.x, 0.0f); v.y = fmaxf(v.y + b.y, 0.0f);
    v.z = fmaxf(v.z + b.z, 0.0f); v.w = fmaxf(v.w + b.w, 0.0f);
    return v;
}

// ---------------- the single mega kernel ----------------
__global__ void __launch_bounds__(NTHR, 1)
mega7_kernel(const float* __restrict__ obs,
             const float* __restrict__ tf,
             const float* __restrict__ fc_w1, const float* __restrict__ b1,
             const float* __restrict__ fc_w2, const float* __restrict__ b2,
             const float* __restrict__ fc_w3, const float* __restrict__ b3,
             const float* __restrict__ Wf, const float* __restrict__ Wb,
             const float* __restrict__ bvec,
             const float* __restrict__ li,
             const float* __restrict__ gs_w1, const float* __restrict__ gs_b1,
             const float* __restrict__ gs_w2, const float* __restrict__ gs_b2,
             const float* __restrict__ gt_w1, const float* __restrict__ gt_b1,
             const float* __restrict__ gt_w2, const float* __restrict__ gt_b2,
             const float* __restrict__ Bm,
             float* __restrict__ out) {
    extern __shared__ float sm[];
    float* sY   = sm;
    float* sX10 = sm + 12288;
    float* sX9  = sm + 24576;

    const int tid = threadIdx.x, bid = blockIdx.x;
    const int gt = bid * NTHR + tid;
    const int lane = tid & 31;
    const int gw = gt >> 5;             // global warp 0..2367

    // ======== P0: obs gather, out-tail zero, sph split-K (coalesced), tph ==
    for (int i = gt; i < 16384 + 36864; i += NT) {
        if (i < 16384) {
            int m = i >> 13, k = i & 8191;
            int n = k >> 3, d = k & 7;
            g_obs2[i] = obs[n * 96 + d * 12 + 9 + m];
        } else {
            out[12288 + (i - 16384)] = 0.0f;
        }
    }
    if (gt < 24576) {                       // sph: 12 tau x 8 kc x 256 t
        int t = gt & 255;
        int rr = gt >> 8;                   // 0..95
        int tau = rr / 8, kc = rr & 7;
        const float* lr = li + tau * 1024 + kc * 128;
        const float* w  = gs_w1 + (size_t)(kc * 128) * 256 + t;
        float acc = 0.0f;
#pragma unroll 16
        for (int k = 0; k < 128; ++k) acc += lr[k] * w[(size_t)k * 256];
        atomicAdd(&g_sph[tau * 256 + t], acc);
    } else if (gt < 24832) {                // tph
        int t = gt - 24576;
        float acc = 0.0f;
#pragma unroll
        for (int k = 0; k < 36; ++k) acc += tf[k] * gt_w1[k * 256 + t];
        g_tph[t] = acc;                     // bias at read
    }
    grid_barrier(0);

    // ======== P1: u (blocks 0..47) || gemv1 (48..147: 1600 warps exact) ====
    if (bid < 48) {
        int lw = bid * 16 + (tid >> 5);     // 0..767
        for (int task = lw; task < 3072; task += 768) {
            int n = task / 3, c = task - n * 3;
            int j = n * 12 + 9 + c;
            float wg[8], wt[8], bg[8];
#pragma unroll
            for (int i = 0; i < 8; ++i) {
                int k = lane + 32 * i;
                wg[i] = gs_w2[(size_t)k * 12288 + j];
                wt[i] = gt_w2[(size_t)k * 12288 + j];
                bg[i] = gs_b1[k];
            }
            float tp = 0.0f;
#pragma unroll
            for (int i = 0; i < 8; ++i) {
                int k = lane + 32 * i;
                tp += fmaxf(g_tph[k] + gt_b1[k], 0.0f) * wt[i];
            }
#pragma unroll
            for (int o = 16; o; o >>= 1) tp += __shfl_xor_sync(0xffffffffu, tp, o);
            float tpv = fmaxf(tp + gt_b2[j], 0.0f);
            float bsp = gs_b2[j];
#pragma unroll
            for (int tau = 0; tau < 12; ++tau) {
                float sp = 0.0f;
#pragma unroll
                for (int i = 0; i < 8; ++i)
                    sp += fmaxf(g_sph[tau * 256 + lane + 32 * i] + bg[i], 0.0f) * wg[i];
#pragma unroll
                for (int o = 16; o; o >>= 1) sp += __shfl_xor_sync(0xffffffffu, sp, o);
                if (lane == tau)
                    g_U[c * 12288 + n * 12 + tau] = fmaxf(sp + bsp, 0.0f) + tpv;
            }
        }
    } else {
        int w = (bid - 48) * 16 + (tid >> 5);   // 0..1599
        int cb = w & 15;
        int kc = w >> 4;                    // 0..99
        int col = (cb * 32 + lane) * 4;
        if (kc < 92)
            gemv_wtile<8192, 2048, 82, false>(g_obs2, b1, fc_w1, g_s1,
                                              col, kc * 82);
        else
            gemv_wtile<8192, 2048, 81, false>(g_obs2, b1, fc_w1, g_s1,
                                              col, 7544 + (kc - 92) * 81);
    }
    grid_barrier(1);

    // ======== P2: gemv2 — 16 cb x 148 kc = 2368 warps exactly ==============
    {
        int cb = gw & 15;
        int kc = gw >> 4;                   // 0..147
        int col = (cb * 32 + lane) * 4;
        if (kc < 124)
            gemv_wtile<2048, 2048, 14, true>(g_s1, b1, fc_w2, g_s2,
                                             col, kc * 14);
        else
            gemv_wtile<2048, 2048, 13, true>(g_s1, b1, fc_w2, g_s2,
                                             col, 1736 + (kc - 124) * 13);
    }
    grid_barrier(2);

    // ======== P3: gemv3 — 96 cb x 24 kc = 2304 warps; 32 warps do Y ========
    if (gw < 2304) {
        int cb = gw % 96;
        int kc = gw / 96;                   // 0..23
        int col = (cb * 32 + lane) * 4;
        if (kc < 16)
            gemv_wtile<2048, 12288, 86, true>(g_s2, b2, fc_w3, g_s3,
                                              col, kc * 86);
        else
            gemv_wtile<2048, 12288, 84, true>(g_s2, b2, fc_w3, g_s3,
                                              col, 1376 + (kc - 16) * 84);
    } else if (gw < 2336) {
        int n = (gw - 2304) * 32 + lane;    // 0..1023
        float u[12];
#pragma unroll
        for (int q = 0; q < 12; ++q) u[q] = g_U[12288 + n * 12 + q];
#pragma unroll
        for (int p = 0; p < 12; ++p) {
            float acc = 0.0f;
#pragma unroll
            for (int q = 0; q < 12; ++q) acc += Bm[p * 12 + q] * u[q];
            g_Y[n * 12 + p] = acc;
        }
    }
    grid_barrier(3);

    // ======== P4: stage Y/X in smem, fused exp-adjacency + SpMM ============
    for (int i = tid; i < 12288 / 4; i += NTHR) {
        ((float4*)sY)[i] = ((const float4*)g_Y)[i];
        float4 bb = ((const float4*)b3)[i % 3072];
        ((float4*)sX10)[i] = relu4b(((const float4*)(g_s3 + 12288))[i], bb);
        ((float4*)sX9)[i]  = relu4b(((const float4*)g_s3)[i], bb);
    }
    __syncthreads();
    for (int task = gw; task < 3072; task += NWARP) {  // 1-2 rows per warp
        int ap = task >> 10;                // 0..2
        int i = task & 1023;
        int cidx = (ap == 0) ? 1 : (ap == 1 ? 0 : 2);   // a = 10,9,11
        const float* sX = (ap == 0) ? sX10 : sX9;
        float u[12];
#pragma unroll
        for (int q = 0; q < 12; ++q) u[q] = g_U[cidx * 12288 + i * 12 + q];
        float g[12];
#pragma unroll
        for (int q = 0; q < 12; ++q) g[q] = 0.0f;
        float rs = 0.0f;
        for (int j = lane; j < 1024; j += 32) {
            const float4* yr = (const float4*)(sY + j * 12);
            float4 ya = yr[0], yb = yr[1], yc = yr[2];
            float s = u[0]*ya.x + u[1]*ya.y + u[2] *ya.z + u[3] *ya.w
                    + u[4]*yb.x + u[5]*yb.y + u[6] *yb.z + u[7] *yb.w
                    + u[8]*yc.x + u[9]*yc.y + u[10]*yc.z + u[11]*yc.w;
            s = (s >= 0.05f) ? s : 0.0f;
            float e = __expf(s);
            rs += e;
            const float4* xr = (const float4*)(sX + j * 12);
            float4 xa = xr[0], xb = xr[1], xc = xr[2];
            g[0] += e*xa.x; g[1] += e*xa.y; g[2] += e*xa.z; g[3] += e*xa.w;
            g[4] += e*xb.x; g[5] += e*xb.y; g[6] += e*xb.z; g[7] += e*xb.w;
            g[8] += e*xc.x; g[9] += e*xc.y; g[10]+= e*xc.z; g[11]+= e*xc.w;
        }
#pragma unroll
        for (int o = 16; o; o >>= 1) {
            rs += __shfl_xor_sync(0xffffffffu, rs, o);
#pragma unroll
            for (int q = 0; q < 12; ++q)
                g[q] += __shfl_xor_sync(0xffffffffu, g[q], o);
        }
        if (lane == 0) {
            float inv = 1.0f / rs;
            float* G = g_G + task * 12;
#pragma unroll
            for (int q = 0; q < 12; ++q) G[q] = g[q] * inv;
        }
    }
    grid_barrier(4);

    // ======== P5: combine + zero accumulators ==============================
    if (gt < 12288 + 35840) {
        int idx = gt;
        if (idx < 12288) {
            int n = idx / 12, f = idx % 12;
            float acc1 = bvec[f], acc2 = bvec[f];
#pragma unroll
            for (int q = 0; q < 12; ++q) {
                acc1 += g_G[n * 12 + q] * (Wf[q * 12 + f] + Wb[q * 12 + f]);
                acc2 += g_G[(1024 + n) * 12 + q] * Wf[144 + q * 12 + f]
                      + g_G[(2048 + n) * 12 + q] * Wb[144 + q * 12 + f];
            }
            out[idx] = fmaxf(acc1, 0.0f) + fmaxf(acc2, 0.0f);
        } else {
            int i = idx - 12288;
            if (i < 4096)        g_s1[i] = 0.0f;
            else if (i < 8192)   g_s2[i - 4096] = 0.0f;
            else if (i < 32768)  g_s3[i - 8192] = 0.0f;
            else                 g_sph[i - 32768] = 0.0f;
        }
    }
}

// ---------------- launch ----------------
extern "C" void kernel_launch(void* const* d_in, const int* in_sizes, int n_in,
                              void* d_out, int out_size) {
    const float* obs    = (const float*)d_in[0];
    const float* tf     = (const float*)d_in[1];
    const float* fc_w1  = (const float*)d_in[2];
    const float* fc_b1  = (const float*)d_in[3];
    const float* fc_w2  = (const float*)d_in[4];
    const float* fc_b2  = (const float*)d_in[5];
    const float* fc_w3  = (const float*)d_in[6];
    const float* fc_b3  = (const float*)d_in[7];
    const float* Wf     = (const float*)d_in[8];
    const float* Wb     = (const float*)d_in[9];
    const float* bvec   = (const float*)d_in[10];
    const float* li     = (const float*)d_in[11];
    const float* gs_w1  = (const float*)d_in[12];
    const float* gs_b1  = (const float*)d_in[13];
    const float* gs_w2  = (const float*)d_in[14];
    const float* gs_b2  = (const float*)d_in[15];
    const float* gt_w1  = (const float*)d_in[16];
    const float* gt_b1  = (const float*)d_in[17];
    const float* gt_w2  = (const float*)d_in[18];
    const float* gt_b2  = (const float*)d_in[19];
    const float* Bm     = (const float*)d_in[20];
    float* out = (float*)d_out;

    cudaFuncSetAttribute(mega7_kernel,
                         cudaFuncAttributeMaxDynamicSharedMemorySize,
                         SMEM_FLOATS * sizeof(float));

    mega7_kernel<<<NBLK, NTHR, SMEM_FLOATS * sizeof(float)>>>(
        obs, tf, fc_w1, fc_b1, fc_w2, fc_b2, fc_w3, fc_b3,
        Wf, Wb, bvec, li, gs_w1, gs_b1, gs_w2, gs_b2,
        gt_w1, gt_b1, gt_w2, gt_b2, Bm, out);
}